// round 7
// baseline (speedup 1.0000x reference)
#include <cuda_runtime.h>

// Fused CBF-QP controller. R7: bias-fold into packed dot init (FADD->MOV off
// the fma pipe), j-pair packed uu/L accumulators, occupancy 2->3 blocks/SM.

namespace {

constexpr int S_DIM = 16;
constexpr int H_DIM = 128;
constexpr int A_DIM = 4;
constexpr float QP_EPS = 1e-8f;

using u64 = unsigned long long;

struct CB {
    ulonglong2 Wc1T[H_DIM * 4];        // [j][0..3]; Wc1T[j][k] = Wc1[k*H + j]
    ulonglong2 Wc2P[H_DIM / 2 * 2];    // [i*2+0]=(a01 pairs),[i*2+1]=(a23): (Wc2[2i][a],Wc2[2i+1][a])
    ulonglong2 WfT[S_DIM * 4];         // [sp][0..3]; WfT[sp][k] = Wf[k*S + sp]
    ulonglong2 WgP[S_DIM * A_DIM * 4]; // [(sp*4+a)][0..3]: k-pair packed float2 x8
    float4 bg4[S_DIM];                 // bg as [sp][a]
    float  bf[S_DIM];
    float  bc2[A_DIM];
    float  bh2;
    float  pad[3];
};

__constant__ CB cb;
__device__   CB g_scratch;

__global__ void prep_kernel(const float* __restrict__ Wc1,
                            const float* __restrict__ Wc2,
                            const float* __restrict__ Wf,
                            const float* __restrict__ Wg,
                            const float* __restrict__ bg,
                            const float* __restrict__ bf,
                            const float* __restrict__ bc2,
                            const float* __restrict__ bh2)
{
    const int tid = blockIdx.x * blockDim.x + threadIdx.x;
    const int nthr = gridDim.x * blockDim.x;

    for (int idx = tid; idx < H_DIM * S_DIM; idx += nthr) {
        const int j = idx >> 4, k = idx & 15;
        reinterpret_cast<float*>(g_scratch.Wc1T)[j * 16 + k] = Wc1[k * H_DIM + j];
    }
    // Wc2 j-pair packed: float2[(i*4+a)] = (Wc2[2i][a], Wc2[2i+1][a])
    for (int idx = tid; idx < (H_DIM / 2) * A_DIM; idx += nthr) {
        const int i = idx >> 2, a = idx & 3;
        reinterpret_cast<float2*>(g_scratch.Wc2P)[idx] =
            make_float2(Wc2[(2 * i) * A_DIM + a], Wc2[(2 * i + 1) * A_DIM + a]);
    }
    for (int idx = tid; idx < S_DIM * S_DIM; idx += nthr) {
        const int sp = idx >> 4, k = idx & 15;
        reinterpret_cast<float*>(g_scratch.WfT)[sp * 16 + k] = Wf[k * S_DIM + sp];
    }
    for (int idx = tid; idx < S_DIM * A_DIM * 8; idx += nthr) {
        const int spa = idx >> 3, m = idx & 7;
        const float lo = Wg[(2 * m)     * (S_DIM * A_DIM) + spa];
        const float hi = Wg[(2 * m + 1) * (S_DIM * A_DIM) + spa];
        reinterpret_cast<float2*>(g_scratch.WgP)[spa * 8 + m] = make_float2(lo, hi);
    }
    for (int idx = tid; idx < S_DIM * A_DIM; idx += nthr)
        reinterpret_cast<float*>(g_scratch.bg4)[idx] = bg[idx];
    if (tid < S_DIM) g_scratch.bf[tid]  = bf[tid];
    if (tid < A_DIM) g_scratch.bc2[tid] = bc2[tid];
    if (tid == 0)    g_scratch.bh2      = bh2[0];
}

__device__ __forceinline__ u64 pack2(float lo, float hi) {
    u64 r; asm("mov.b64 %0, {%1, %2};" : "=l"(r) : "f"(lo), "f"(hi)); return r;
}
__device__ __forceinline__ void unpack2(u64 v, float& lo, float& hi) {
    asm("mov.b64 {%0, %1}, %2;" : "=f"(lo), "=f"(hi) : "l"(v));
}
__device__ __forceinline__ u64 fma2(u64 a, u64 b, u64 c) {
    u64 d; asm("fma.rn.f32x2 %0, %1, %2, %3;" : "=l"(d) : "l"(a), "l"(b), "l"(c)); return d;
}
__device__ __forceinline__ u64 add2(u64 a, u64 b) {
    u64 d; asm("add.rn.f32x2 %0, %1, %2;" : "=l"(d) : "l"(a), "l"(b)); return d;
}
__device__ __forceinline__ u64 mul2(u64 a, u64 b) {
    u64 d; asm("mul.rn.f32x2 %0, %1, %2;" : "=l"(d) : "l"(a), "l"(b)); return d;
}

__device__ __forceinline__ float hw_tanh(float x) {
    float y; asm("tanh.approx.f32 %0, %1;" : "=f"(y) : "f"(x));
    return y;
}

// dot(s, w) with bias folded into the packed accumulator init (bias2 = (bias,0)).
__device__ __forceinline__ float dot16b(const u64* s2,
                                        ulonglong2 w0, ulonglong2 w1,
                                        ulonglong2 w2, ulonglong2 w3, u64 bias2) {
    u64 a0 = fma2(s2[0], w0.x, bias2);
    u64 a1 = mul2(s2[4], w2.x);
    a0 = fma2(s2[1], w0.y, a0);
    a1 = fma2(s2[5], w2.y, a1);
    a0 = fma2(s2[2], w1.x, a0);
    a1 = fma2(s2[6], w3.x, a1);
    a0 = fma2(s2[3], w1.y, a0);
    a1 = fma2(s2[7], w3.y, a1);
    u64 s = add2(a0, a1);
    float lo, hi; unpack2(s, lo, hi);
    return lo + hi;
}

__global__ void __launch_bounds__(256, 3)
cbf_fused(const float* __restrict__ state,
          const float* __restrict__ Wh1, const float* __restrict__ bc1,
          const float* __restrict__ bh1, const float* __restrict__ wh2,
          float* __restrict__ out, int total)
{
    __shared__ float4 sWh1[H_DIM][4];     // Wh1^T (LDS port)
    __shared__ float4 sBC[H_DIM / 2];     // (bc1[2i], bc1[2i+1], bh1[2i], bh1[2i+1])
    __shared__ u64    sWh2p[H_DIM / 2];   // ( wh2[2i],  wh2[2i+1])
    __shared__ u64    sWh2n[H_DIM / 2];   // (-wh2[2i], -wh2[2i+1])

    const int tid = threadIdx.x;

    for (int idx = tid; idx < H_DIM * S_DIM; idx += blockDim.x) {
        const int j = idx >> 4, k = idx & 15;
        reinterpret_cast<float*>(sWh1)[idx] = Wh1[k * H_DIM + j];
    }
    for (int i = tid; i < H_DIM / 2; i += blockDim.x) {
        sBC[i] = make_float4(bc1[2 * i], bc1[2 * i + 1], bh1[2 * i], bh1[2 * i + 1]);
        const float wa = wh2[2 * i], wb = wh2[2 * i + 1];
        sWh2p[i] = pack2(wa, wb);
        sWh2n[i] = pack2(-wa, -wb);
    }
    __syncthreads();

    const int row = blockIdx.x * blockDim.x + tid;
    if (row >= total) return;

    u64 s2[8];
    {
        const ulonglong2* sp2 =
            reinterpret_cast<const ulonglong2*>(state + (size_t)row * S_DIM);
        const ulonglong2 a = sp2[0], b = sp2[1], c = sp2[2], d = sp2[3];
        s2[0] = a.x; s2[1] = a.y; s2[2] = b.x; s2[3] = b.y;
        s2[4] = c.x; s2[5] = c.y; s2[6] = d.x; s2[7] = d.y;
    }

    u64 uu0p = 0ull, uu1p = 0ull, uu2p = 0ull, uu3p = 0ull;  // packed over j-pairs
    u64 hval2 = 0ull;                                        // packed over j-pairs
    u64 dh2[8];
    #pragma unroll
    for (int m = 0; m < 8; ++m) dh2[m] = 0ull;

    #pragma unroll 2
    for (int i = 0; i < H_DIM / 2; ++i) {
        const int j = 2 * i;
        const float4 bc = sBC[i];                    // LDS

        // controller dots for j, j+1 (constant port)
        const ulonglong2 cA0 = cb.Wc1T[j * 4 + 0], cA1 = cb.Wc1T[j * 4 + 1];
        const ulonglong2 cA2 = cb.Wc1T[j * 4 + 2], cA3 = cb.Wc1T[j * 4 + 3];
        const float t1a = hw_tanh(dot16b(s2, cA0, cA1, cA2, cA3, pack2(bc.x, 0.0f)));
        const ulonglong2 cB0 = cb.Wc1T[j * 4 + 4], cB1 = cb.Wc1T[j * 4 + 5];
        const ulonglong2 cB2 = cb.Wc1T[j * 4 + 6], cB3 = cb.Wc1T[j * 4 + 7];
        const float t1b = hw_tanh(dot16b(s2, cB0, cB1, cB2, cB3, pack2(bc.y, 0.0f)));
        const u64 t1p = pack2(t1a, t1b);
        const ulonglong2 c2lo = cb.Wc2P[i * 2 + 0];  // a=0,1 pairs
        const ulonglong2 c2hi = cb.Wc2P[i * 2 + 1];  // a=2,3 pairs
        uu0p = fma2(t1p, c2lo.x, uu0p);
        uu1p = fma2(t1p, c2lo.y, uu1p);
        uu2p = fma2(t1p, c2hi.x, uu2p);
        uu3p = fma2(t1p, c2hi.y, uu3p);

        // CBF branch j (shared port); dh done before loading j+1 weights (reg pressure)
        const ulonglong2* whA = reinterpret_cast<const ulonglong2*>(&sWh1[j][0]);
        const ulonglong2 hA0 = whA[0], hA1 = whA[1], hA2 = whA[2], hA3 = whA[3];
        const float t2a = hw_tanh(dot16b(s2, hA0, hA1, hA2, hA3, pack2(bc.z, 0.0f)));
        const float wja = reinterpret_cast<const float2*>(&sWh2p[i])->x;
        const float cja = fmaf(-t2a * t2a, wja, wja);
        const u64 cjaP = pack2(cja, cja);
        dh2[0] = fma2(cjaP, hA0.x, dh2[0]); dh2[1] = fma2(cjaP, hA0.y, dh2[1]);
        dh2[2] = fma2(cjaP, hA1.x, dh2[2]); dh2[3] = fma2(cjaP, hA1.y, dh2[3]);
        dh2[4] = fma2(cjaP, hA2.x, dh2[4]); dh2[5] = fma2(cjaP, hA2.y, dh2[5]);
        dh2[6] = fma2(cjaP, hA3.x, dh2[6]); dh2[7] = fma2(cjaP, hA3.y, dh2[7]);

        // CBF branch j+1
        const ulonglong2* whB = reinterpret_cast<const ulonglong2*>(&sWh1[j + 1][0]);
        const ulonglong2 hB0 = whB[0], hB1 = whB[1], hB2 = whB[2], hB3 = whB[3];
        const float t2b = hw_tanh(dot16b(s2, hB0, hB1, hB2, hB3, pack2(bc.w, 0.0f)));
        const float wjb = reinterpret_cast<const float2*>(&sWh2p[i])->y;
        const float cjb = fmaf(-t2b * t2b, wjb, wjb);
        const u64 cjbP = pack2(cjb, cjb);
        dh2[0] = fma2(cjbP, hB0.x, dh2[0]); dh2[1] = fma2(cjbP, hB0.y, dh2[1]);
        dh2[2] = fma2(cjbP, hB1.x, dh2[2]); dh2[3] = fma2(cjbP, hB1.y, dh2[3]);
        dh2[4] = fma2(cjbP, hB2.x, dh2[4]); dh2[5] = fma2(cjbP, hB2.y, dh2[5]);
        dh2[6] = fma2(cjbP, hB3.x, dh2[6]); dh2[7] = fma2(cjbP, hB3.y, dh2[7]);

        // hval packed over the j-pair
        hval2 = fma2(pack2(t2a, t2b), sWh2p[i], hval2);
    }

    float dh[16];
    #pragma unroll
    for (int m = 0; m < 8; ++m) unpack2(dh2[m], dh[2 * m], dh[2 * m + 1]);

    // right = h + dh . f   (Wf from constant, bias folded)
    float hlo, hhi; unpack2(hval2, hlo, hhi);
    float right = hlo + hhi + cb.bh2;
    #pragma unroll
    for (int sp = 0; sp < S_DIM; ++sp) {
        const ulonglong2 f0 = cb.WfT[sp * 4 + 0];
        const ulonglong2 f1 = cb.WfT[sp * 4 + 1];
        const ulonglong2 f2 = cb.WfT[sp * 4 + 2];
        const ulonglong2 f3 = cb.WfT[sp * 4 + 3];
        right = fmaf(dh[sp], dot16b(s2, f0, f1, f2, f3, pack2(cb.bf[sp], 0.0f)), right);
    }

    // L[a] = sum_sp dh[sp] * g[sp][a], accumulated packed over sp-pairs via dh2[m]
    u64 L0p = 0ull, L1p = 0ull, L2p = 0ull, L3p = 0ull;
    #pragma unroll
    for (int m = 0; m < 8; ++m) {
        const int sp0 = 2 * m, sp1 = 2 * m + 1;
        const float4 bg0 = cb.bg4[sp0];
        const float4 bg1 = cb.bg4[sp1];
        const float b0a[4] = {bg0.x, bg0.y, bg0.z, bg0.w};
        const float b1a[4] = {bg1.x, bg1.y, bg1.z, bg1.w};
        u64 Lacc[4];
        #pragma unroll
        for (int a = 0; a < A_DIM; ++a) {
            const int spa0 = sp0 * 4 + a, spa1 = sp1 * 4 + a;
            const ulonglong2 p0 = cb.WgP[spa0 * 4 + 0], p1 = cb.WgP[spa0 * 4 + 1];
            const ulonglong2 p2 = cb.WgP[spa0 * 4 + 2], p3 = cb.WgP[spa0 * 4 + 3];
            const float g0 = dot16b(s2, p0, p1, p2, p3, pack2(b0a[a], 0.0f));
            const ulonglong2 q0 = cb.WgP[spa1 * 4 + 0], q1 = cb.WgP[spa1 * 4 + 1];
            const ulonglong2 q2 = cb.WgP[spa1 * 4 + 2], q3 = cb.WgP[spa1 * 4 + 3];
            const float g1 = dot16b(s2, q0, q1, q2, q3, pack2(b1a[a], 0.0f));
            Lacc[a] = pack2(g0, g1);
        }
        L0p = fma2(dh2[m], Lacc[0], L0p);
        L1p = fma2(dh2[m], Lacc[1], L1p);
        L2p = fma2(dh2[m], Lacc[2], L2p);
        L3p = fma2(dh2[m], Lacc[3], L3p);
    }
    float L[4];
    { float lo, hi;
      unpack2(L0p, lo, hi); L[0] = lo + hi;
      unpack2(L1p, lo, hi); L[1] = lo + hi;
      unpack2(L2p, lo, hi); L[2] = lo + hi;
      unpack2(L3p, lo, hi); L[3] = lo + hi; }

    // QP epilogue: u_unc = 2*(t1@Wc2 + bc2); viol = -L.u - right; u = u_unc + lam*L
    float u[4];
    { float lo, hi;
      unpack2(uu0p, lo, hi); u[0] = 2.0f * (lo + hi + cb.bc2[0]);
      unpack2(uu1p, lo, hi); u[1] = 2.0f * (lo + hi + cb.bc2[1]);
      unpack2(uu2p, lo, hi); u[2] = 2.0f * (lo + hi + cb.bc2[2]);
      unpack2(uu3p, lo, hi); u[3] = 2.0f * (lo + hi + cb.bc2[3]); }

    const float viol = -(L[0]*u[0] + L[1]*u[1] + L[2]*u[2] + L[3]*u[3]) - right;
    const float den  = L[0]*L[0] + L[1]*L[1] + L[2]*L[2] + L[3]*L[3] + QP_EPS;
    const float lam  = viol > 0.0f ? (viol / den) : 0.0f;

    float4 res;
    res.x = fmaf(lam, L[0], u[0]);
    res.y = fmaf(lam, L[1], u[1]);
    res.z = fmaf(lam, L[2], u[2]);
    res.w = fmaf(lam, L[3], u[3]);
    reinterpret_cast<float4*>(out)[row] = res;
}

} // namespace

extern "C" void kernel_launch(void* const* d_in, const int* in_sizes, int n_in,
                              void* d_out, int out_size) {
    const float* state = (const float*)d_in[0];
    const float* Wc1   = (const float*)d_in[1];
    const float* bc1   = (const float*)d_in[2];
    const float* Wc2   = (const float*)d_in[3];
    const float* bc2   = (const float*)d_in[4];
    const float* Wh1   = (const float*)d_in[5];
    const float* bh1   = (const float*)d_in[6];
    const float* wh2   = (const float*)d_in[7];
    const float* bh2   = (const float*)d_in[8];
    const float* Wf    = (const float*)d_in[9];
    const float* bf    = (const float*)d_in[10];
    const float* Wg    = (const float*)d_in[11];
    const float* bg    = (const float*)d_in[12];

    // 1) pack/transpose weights into device scratch
    prep_kernel<<<16, 256>>>(Wc1, Wc2, Wf, Wg, bg, bf, bc2, bh2);

    // 2) scratch -> constant bank (D2D async memcpy, graph-capturable)
    void* scratch_ptr = nullptr;
    void* cb_ptr = nullptr;
    cudaGetSymbolAddress(&scratch_ptr, g_scratch);
    cudaGetSymbolAddress(&cb_ptr, cb);
    cudaMemcpyAsync(cb_ptr, scratch_ptr, sizeof(CB), cudaMemcpyDeviceToDevice, 0);

    // 3) main kernel
    const int total = in_sizes[0] / 16;   // B*T rows
    const int threads = 256;
    const int blocks = (total + threads - 1) / threads;
    cbf_fused<<<blocks, threads>>>(state, Wh1, bc1, bh1, wh2, (float*)d_out, total);
}

// round 8
// speedup vs baseline: 1.0822x; 1.0822x over previous
#include <cuda_runtime.h>

// Fused CBF-QP controller — exactly the R6 winner (f32x2 math, dual-port
// weights, hw tanh) with ONE change: __launch_bounds__(256,3) to lift
// occupancy from 2 to 3 blocks/SM (regs 86 -> <=85).

namespace {

constexpr int S_DIM = 16;
constexpr int H_DIM = 128;
constexpr int A_DIM = 4;
constexpr float QP_EPS = 1e-8f;

using u64 = unsigned long long;

struct CB {
    ulonglong2 Wc1T[H_DIM * 4];        // [j][0..3]; Wc1T[j][k] = Wc1[k*H + j]
    ulonglong2 Wc2v[H_DIM];            // Wc2 row j (4 floats)
    ulonglong2 WfT[S_DIM * 4];         // [sp][0..3]; WfT[sp][k] = Wf[k*S + sp]
    ulonglong2 WgP[S_DIM * A_DIM * 4]; // [(sp*4+a)][0..3]: k-pair packed float2 x8
    float4 bg4[S_DIM];                 // bg as [sp][a]
    float  bf[S_DIM];
    float  bc2[A_DIM];
    float  bh2;
    float  pad[3];
};

__constant__ CB cb;
__device__   CB g_scratch;

__global__ void prep_kernel(const float* __restrict__ Wc1,
                            const float* __restrict__ Wc2,
                            const float* __restrict__ Wf,
                            const float* __restrict__ Wg,
                            const float* __restrict__ bg,
                            const float* __restrict__ bf,
                            const float* __restrict__ bc2,
                            const float* __restrict__ bh2)
{
    const int tid = blockIdx.x * blockDim.x + threadIdx.x;
    const int nthr = gridDim.x * blockDim.x;

    for (int idx = tid; idx < H_DIM * S_DIM; idx += nthr) {
        const int j = idx >> 4, k = idx & 15;
        reinterpret_cast<float*>(g_scratch.Wc1T)[j * 16 + k] = Wc1[k * H_DIM + j];
    }
    for (int idx = tid; idx < H_DIM * 4; idx += nthr)
        reinterpret_cast<float*>(g_scratch.Wc2v)[idx] = Wc2[idx];
    for (int idx = tid; idx < S_DIM * S_DIM; idx += nthr) {
        const int sp = idx >> 4, k = idx & 15;
        reinterpret_cast<float*>(g_scratch.WfT)[sp * 16 + k] = Wf[k * S_DIM + sp];
    }
    for (int idx = tid; idx < S_DIM * A_DIM * 8; idx += nthr) {
        const int spa = idx >> 3, m = idx & 7;
        const float lo = Wg[(2 * m)     * (S_DIM * A_DIM) + spa];
        const float hi = Wg[(2 * m + 1) * (S_DIM * A_DIM) + spa];
        reinterpret_cast<float2*>(g_scratch.WgP)[spa * 8 + m] = make_float2(lo, hi);
    }
    for (int idx = tid; idx < S_DIM * A_DIM; idx += nthr)
        reinterpret_cast<float*>(g_scratch.bg4)[idx] = bg[idx];
    if (tid < S_DIM) g_scratch.bf[tid]  = bf[tid];
    if (tid < A_DIM) g_scratch.bc2[tid] = bc2[tid];
    if (tid == 0)    g_scratch.bh2      = bh2[0];
}

__device__ __forceinline__ u64 pack2(float lo, float hi) {
    u64 r; asm("mov.b64 %0, {%1, %2};" : "=l"(r) : "f"(lo), "f"(hi)); return r;
}
__device__ __forceinline__ void unpack2(u64 v, float& lo, float& hi) {
    asm("mov.b64 {%0, %1}, %2;" : "=f"(lo), "=f"(hi) : "l"(v));
}
__device__ __forceinline__ u64 fma2(u64 a, u64 b, u64 c) {
    u64 d; asm("fma.rn.f32x2 %0, %1, %2, %3;" : "=l"(d) : "l"(a), "l"(b), "l"(c)); return d;
}
__device__ __forceinline__ u64 add2(u64 a, u64 b) {
    u64 d; asm("add.rn.f32x2 %0, %1, %2;" : "=l"(d) : "l"(a), "l"(b)); return d;
}
__device__ __forceinline__ u64 mul2(u64 a, u64 b) {
    u64 d; asm("mul.rn.f32x2 %0, %1, %2;" : "=l"(d) : "l"(a), "l"(b)); return d;
}

// Hardware tanh: single MUFU op, max rel err ~5e-4 (threshold is 1e-3).
__device__ __forceinline__ float hw_tanh(float x) {
    float y; asm("tanh.approx.f32 %0, %1;" : "=f"(y) : "f"(x));
    return y;
}

__device__ __forceinline__ float dot16p(const u64* s2,
                                        ulonglong2 w0, ulonglong2 w1,
                                        ulonglong2 w2, ulonglong2 w3, float bias) {
    u64 a0 = mul2(s2[0], w0.x);
    u64 a1 = mul2(s2[4], w2.x);
    a0 = fma2(s2[1], w0.y, a0);
    a1 = fma2(s2[5], w2.y, a1);
    a0 = fma2(s2[2], w1.x, a0);
    a1 = fma2(s2[6], w3.x, a1);
    a0 = fma2(s2[3], w1.y, a0);
    a1 = fma2(s2[7], w3.y, a1);
    u64 sum = add2(a0, a1);
    float lo, hi; unpack2(sum, lo, hi);
    return bias + lo + hi;
}

__global__ void __launch_bounds__(256, 3)
cbf_fused(const float* __restrict__ state,
          const float* __restrict__ Wh1, const float* __restrict__ bc1,
          const float* __restrict__ bh1, const float* __restrict__ wh2,
          float* __restrict__ out, int total)
{
    __shared__ float4 sWh1[H_DIM][4];   // Wh1^T (LDS port)
    __shared__ float4 sB[H_DIM];        // (bc1, bh1, wh2, 0)

    const int tid = threadIdx.x;

    for (int idx = tid; idx < H_DIM * S_DIM; idx += blockDim.x) {
        const int j = idx >> 4, k = idx & 15;
        reinterpret_cast<float*>(sWh1)[idx] = Wh1[k * H_DIM + j];
    }
    for (int j = tid; j < H_DIM; j += blockDim.x)
        sB[j] = make_float4(bc1[j], bh1[j], wh2[j], 0.0f);
    __syncthreads();

    const int row = blockIdx.x * blockDim.x + tid;
    if (row >= total) return;

    u64 s2[8];
    {
        const ulonglong2* sp2 =
            reinterpret_cast<const ulonglong2*>(state + (size_t)row * S_DIM);
        const ulonglong2 a = sp2[0], b = sp2[1], c = sp2[2], d = sp2[3];
        s2[0] = a.x; s2[1] = a.y; s2[2] = b.x; s2[3] = b.y;
        s2[4] = c.x; s2[5] = c.y; s2[6] = d.x; s2[7] = d.y;
    }

    u64 uu01 = 0ull, uu23 = 0ull;
    float hval = 0.0f;
    u64 dh2[8];
    #pragma unroll
    for (int m = 0; m < 8; ++m) dh2[m] = 0ull;

    #pragma unroll 4
    for (int j = 0; j < H_DIM; ++j) {
        const float4 bias = sB[j];                         // LDS

        // controller branch: weights from constant port
        const ulonglong2 w0 = cb.Wc1T[j * 4 + 0];
        const ulonglong2 w1 = cb.Wc1T[j * 4 + 1];
        const ulonglong2 w2 = cb.Wc1T[j * 4 + 2];
        const ulonglong2 w3 = cb.Wc1T[j * 4 + 3];
        const float t1 = hw_tanh(dot16p(s2, w0, w1, w2, w3, bias.x));
        const u64 t1p = pack2(t1, t1);
        const ulonglong2 wv2 = cb.Wc2v[j];
        uu01 = fma2(t1p, wv2.x, uu01);
        uu23 = fma2(t1p, wv2.y, uu23);

        // CBF branch: weights from shared port
        const ulonglong2* wh = reinterpret_cast<const ulonglong2*>(&sWh1[j][0]);
        const ulonglong2 h0 = wh[0], h1 = wh[1], h2 = wh[2], h3 = wh[3];
        const float t2 = hw_tanh(dot16p(s2, h0, h1, h2, h3, bias.y));
        hval = fmaf(t2, bias.z, hval);
        const float cj = fmaf(-t2 * t2, bias.z, bias.z);   // (1 - t2^2) * wh2[j]
        const u64 cj2 = pack2(cj, cj);
        dh2[0] = fma2(cj2, h0.x, dh2[0]); dh2[1] = fma2(cj2, h0.y, dh2[1]);
        dh2[2] = fma2(cj2, h1.x, dh2[2]); dh2[3] = fma2(cj2, h1.y, dh2[3]);
        dh2[4] = fma2(cj2, h2.x, dh2[4]); dh2[5] = fma2(cj2, h2.y, dh2[5]);
        dh2[6] = fma2(cj2, h3.x, dh2[6]); dh2[7] = fma2(cj2, h3.y, dh2[7]);
    }

    float dh[16];
    #pragma unroll
    for (int m = 0; m < 8; ++m) unpack2(dh2[m], dh[2 * m], dh[2 * m + 1]);

    // right = h + dh . f   (Wf from constant)
    float right = hval + cb.bh2;
    #pragma unroll
    for (int sp = 0; sp < S_DIM; ++sp) {
        const ulonglong2 f0 = cb.WfT[sp * 4 + 0];
        const ulonglong2 f1 = cb.WfT[sp * 4 + 1];
        const ulonglong2 f2 = cb.WfT[sp * 4 + 2];
        const ulonglong2 f3 = cb.WfT[sp * 4 + 3];
        right = fmaf(dh[sp], dot16p(s2, f0, f1, f2, f3, cb.bf[sp]), right);
    }

    // L[a] = sum_sp dh[sp] * g[sp][a]   (Wg from constant; left = -L)
    float L[4] = {0.f, 0.f, 0.f, 0.f};
    #pragma unroll
    for (int sp = 0; sp < S_DIM; ++sp) {
        const float4 bgv = cb.bg4[sp];
        const float bgarr[4] = {bgv.x, bgv.y, bgv.z, bgv.w};
        const float d = dh[sp];
        #pragma unroll
        for (int a = 0; a < A_DIM; ++a) {
            const int spa = sp * 4 + a;
            const ulonglong2 p0 = cb.WgP[spa * 4 + 0];
            const ulonglong2 p1 = cb.WgP[spa * 4 + 1];
            const ulonglong2 p2 = cb.WgP[spa * 4 + 2];
            const ulonglong2 p3 = cb.WgP[spa * 4 + 3];
            u64 acc = mul2(s2[0], p0.x);
            acc = fma2(s2[1], p0.y, acc);
            acc = fma2(s2[2], p1.x, acc);
            acc = fma2(s2[3], p1.y, acc);
            acc = fma2(s2[4], p2.x, acc);
            acc = fma2(s2[5], p2.y, acc);
            acc = fma2(s2[6], p3.x, acc);
            acc = fma2(s2[7], p3.y, acc);
            float lo, hi; unpack2(acc, lo, hi);
            L[a] = fmaf(d, lo + hi + bgarr[a], L[a]);
        }
    }

    // QP epilogue: u_unc = 2*(t1@Wc2 + bc2); viol = -L.u - right; u = u_unc + lam*L
    float uu0, uu1, uu2, uu3;
    unpack2(uu01, uu0, uu1); unpack2(uu23, uu2, uu3);
    const float u0 = 2.0f * (uu0 + cb.bc2[0]);
    const float u1 = 2.0f * (uu1 + cb.bc2[1]);
    const float u2 = 2.0f * (uu2 + cb.bc2[2]);
    const float u3 = 2.0f * (uu3 + cb.bc2[3]);

    const float viol = -(L[0]*u0 + L[1]*u1 + L[2]*u2 + L[3]*u3) - right;
    const float den  = L[0]*L[0] + L[1]*L[1] + L[2]*L[2] + L[3]*L[3] + QP_EPS;
    const float lam  = viol > 0.0f ? (viol / den) : 0.0f;

    float4 res;
    res.x = fmaf(lam, L[0], u0);
    res.y = fmaf(lam, L[1], u1);
    res.z = fmaf(lam, L[2], u2);
    res.w = fmaf(lam, L[3], u3);
    reinterpret_cast<float4*>(out)[row] = res;
}

} // namespace

extern "C" void kernel_launch(void* const* d_in, const int* in_sizes, int n_in,
                              void* d_out, int out_size) {
    const float* state = (const float*)d_in[0];
    const float* Wc1   = (const float*)d_in[1];
    const float* bc1   = (const float*)d_in[2];
    const float* Wc2   = (const float*)d_in[3];
    const float* bc2   = (const float*)d_in[4];
    const float* Wh1   = (const float*)d_in[5];
    const float* bh1   = (const float*)d_in[6];
    const float* wh2   = (const float*)d_in[7];
    const float* bh2   = (const float*)d_in[8];
    const float* Wf    = (const float*)d_in[9];
    const float* bf    = (const float*)d_in[10];
    const float* Wg    = (const float*)d_in[11];
    const float* bg    = (const float*)d_in[12];

    // 1) pack/transpose weights into device scratch
    prep_kernel<<<16, 256>>>(Wc1, Wc2, Wf, Wg, bg, bf, bc2, bh2);

    // 2) scratch -> constant bank (D2D async memcpy, graph-capturable)
    void* scratch_ptr = nullptr;
    void* cb_ptr = nullptr;
    cudaGetSymbolAddress(&scratch_ptr, g_scratch);
    cudaGetSymbolAddress(&cb_ptr, cb);
    cudaMemcpyAsync(cb_ptr, scratch_ptr, sizeof(CB), cudaMemcpyDeviceToDevice, 0);

    // 3) main kernel
    const int total = in_sizes[0] / 16;   // B*T rows
    const int threads = 256;
    const int blocks = (total + threads - 1) / threads;
    cbf_fused<<<blocks, threads>>>(state, Wh1, bc1, bh1, wh2, (float*)d_out, total);
}